// round 12
// baseline (speedup 1.0000x reference)
#include <cuda_runtime.h>
#include <math_constants.h>
#include <cstdint>

// Problem constants
#define BATCH 8
#define C_IN  512
#define C_OUT 512
#define C_KEY 256
#define NTOK  2048

// ---------------------------------------------------------------------------
// Scratch (__device__ globals; no cudaMalloc allowed)
// ---------------------------------------------------------------------------
__device__ float g_xt[BATCH * NTOK * C_IN];   // xT[b][n][c]
__device__ float g_qt[BATCH * NTOK * C_KEY];  // qT[b][n][ck]
__device__ float g_kt[BATCH * NTOK * C_KEY];  // kT[b][n][ck]
__device__ float g_v [BATCH * C_OUT * NTOK];  // v[b][c][i]  (i contiguous)
__device__ float g_s [BATCH * NTOK * NTOK];   // ST[b][j][i] -> attnT in place

// ---------------------------------------------------------------------------
// tf32 helpers (base-PTX features, valid on .target sm_103)
// ---------------------------------------------------------------------------
__device__ __forceinline__ uint32_t tf32_rna(float f) {
    uint32_t u;
    asm("cvt.rna.tf32.f32 %0, %1;" : "=r"(u) : "f"(f));
    return u;
}

__device__ __forceinline__ void mma_tf32(float* d, const uint32_t* a,
                                         const uint32_t* b)
{
    asm volatile(
        "mma.sync.aligned.m16n8k8.row.col.f32.tf32.tf32.f32 "
        "{%0,%1,%2,%3}, {%4,%5,%6,%7}, {%8,%9}, {%0,%1,%2,%3};"
        : "+f"(d[0]), "+f"(d[1]), "+f"(d[2]), "+f"(d[3])
        : "r"(a[0]), "r"(a[1]), "r"(a[2]), "r"(a[3]),
          "r"(b[0]), "r"(b[1]));
}

// ---------------------------------------------------------------------------
// Tensor-core tf32 GEMM:  D[m,n] = sum_k A[m,k] * B[n,k]  (both K-major)
// 128x128 CTA tile, BK=32, 256 threads (8 warps, each 64x32).
// SPLIT : 2xtf32 precision (hi/lo, 3 MMA passes).
// EPI_T : store C[n][m] instead of C[m][n].
// smem tile layout: row-major [128][36] floats (stride 36 => conflict-free
// fragment LDS.32 and conflict-free float4 STS).
// ---------------------------------------------------------------------------
#define LDK 36
#define TILE_F (128 * LDK)                  // floats per tile
#define SMEM_SINGLE (2 * TILE_F * 4)        // 36864 B
#define SMEM_SPLIT  (4 * TILE_F * 4)        // 73728 B

template <bool SPLIT, bool EPI_T>
__global__ __launch_bounds__(256)
void tc_gemm(const float* __restrict__ A, const float* __restrict__ B,
             float* __restrict__ C,
             int K, int lda, int ldb, int ldc,
             long sA, long sB, long sC)
{
    extern __shared__ float sm[];
    float* Ah = sm;
    float* Bh = sm + TILE_F;
    float* Al = sm + 2 * TILE_F;   // SPLIT only
    float* Bl = sm + 3 * TILE_F;   // SPLIT only

    const int t   = threadIdx.x;
    const int l   = t & 31;
    const int w   = t >> 5;
    const int gid = l >> 2;        // 0..7
    const int tid = l & 3;         // 0..3
    const int wm  = w >> 2;        // 0..1 -> m offset wm*64
    const int wn  = w & 3;         // 0..3 -> n offset wn*32

    A += (long)blockIdx.z * sA;
    B += (long)blockIdx.z * sB;
    C += (long)blockIdx.z * sC;
    const int m0 = blockIdx.y * 128;
    const int n0 = blockIdx.x * 128;

    // loader lanes: 8 lanes cover one row's 32 floats (coalesced 128B)
    const int lr = t >> 3;         // 0..31
    const int lc = (t & 7) * 4;    // 0,4,...,28

    float acc[4][4][4];
#pragma unroll
    for (int mi = 0; mi < 4; ++mi)
#pragma unroll
        for (int ni = 0; ni < 4; ++ni)
#pragma unroll
            for (int c = 0; c < 4; ++c) acc[mi][ni][c] = 0.f;

#pragma unroll 1
    for (int k0 = 0; k0 < K; k0 += 32) {
        __syncthreads();   // previous compute done before overwrite

        // ---- global -> smem (convert to tf32, optional hi/lo split) ----
#pragma unroll
        for (int p = 0; p < 4; ++p) {
            const int r = lr + p * 32;
            // A tile
            {
                float4 v = *(const float4*)(A + (long)(m0 + r) * lda + k0 + lc);
                uint4 h;
                h.x = tf32_rna(v.x); h.y = tf32_rna(v.y);
                h.z = tf32_rna(v.z); h.w = tf32_rna(v.w);
                *(uint4*)&Ah[r * LDK + lc] = h;
                if (SPLIT) {
                    uint4 lo;
                    lo.x = tf32_rna(v.x - __uint_as_float(h.x));
                    lo.y = tf32_rna(v.y - __uint_as_float(h.y));
                    lo.z = tf32_rna(v.z - __uint_as_float(h.z));
                    lo.w = tf32_rna(v.w - __uint_as_float(h.w));
                    *(uint4*)&Al[r * LDK + lc] = lo;
                }
            }
            // B tile
            {
                float4 v = *(const float4*)(B + (long)(n0 + r) * ldb + k0 + lc);
                uint4 h;
                h.x = tf32_rna(v.x); h.y = tf32_rna(v.y);
                h.z = tf32_rna(v.z); h.w = tf32_rna(v.w);
                *(uint4*)&Bh[r * LDK + lc] = h;
                if (SPLIT) {
                    uint4 lo;
                    lo.x = tf32_rna(v.x - __uint_as_float(h.x));
                    lo.y = tf32_rna(v.y - __uint_as_float(h.y));
                    lo.z = tf32_rna(v.z - __uint_as_float(h.z));
                    lo.w = tf32_rna(v.w - __uint_as_float(h.w));
                    *(uint4*)&Bl[r * LDK + lc] = lo;
                }
            }
        }
        __syncthreads();

        // ---- compute: 4 k-steps of 8 ----
#pragma unroll
        for (int s = 0; s < 4; ++s) {
            const int ks = s * 8;

            uint32_t bh[4][2];
#pragma unroll
            for (int ni = 0; ni < 4; ++ni) {
                const float* bp = &Bh[(wn * 32 + ni * 8 + gid) * LDK + ks + tid];
                bh[ni][0] = __float_as_uint(bp[0]);
                bh[ni][1] = __float_as_uint(bp[4]);
            }
            uint32_t ah[4][4];
#pragma unroll
            for (int mi = 0; mi < 4; ++mi) {
                const float* ap = &Ah[(wm * 64 + mi * 16 + gid) * LDK + ks + tid];
                ah[mi][0] = __float_as_uint(ap[0]);
                ah[mi][1] = __float_as_uint(ap[8 * LDK]);
                ah[mi][2] = __float_as_uint(ap[4]);
                ah[mi][3] = __float_as_uint(ap[8 * LDK + 4]);
            }
#pragma unroll
            for (int mi = 0; mi < 4; ++mi)
#pragma unroll
                for (int ni = 0; ni < 4; ++ni)
                    mma_tf32(acc[mi][ni], ah[mi], bh[ni]);

            if (SPLIT) {
                uint32_t bl[4][2];
#pragma unroll
                for (int ni = 0; ni < 4; ++ni) {
                    const float* bp = &Bl[(wn * 32 + ni * 8 + gid) * LDK + ks + tid];
                    bl[ni][0] = __float_as_uint(bp[0]);
                    bl[ni][1] = __float_as_uint(bp[4]);
                }
#pragma unroll
                for (int mi = 0; mi < 4; ++mi)
#pragma unroll
                    for (int ni = 0; ni < 4; ++ni)
                        mma_tf32(acc[mi][ni], ah[mi], bl[ni]);

                uint32_t al[4][4];
#pragma unroll
                for (int mi = 0; mi < 4; ++mi) {
                    const float* ap = &Al[(wm * 64 + mi * 16 + gid) * LDK + ks + tid];
                    al[mi][0] = __float_as_uint(ap[0]);
                    al[mi][1] = __float_as_uint(ap[8 * LDK]);
                    al[mi][2] = __float_as_uint(ap[4]);
                    al[mi][3] = __float_as_uint(ap[8 * LDK + 4]);
                }
#pragma unroll
                for (int mi = 0; mi < 4; ++mi)
#pragma unroll
                    for (int ni = 0; ni < 4; ++ni)
                        mma_tf32(acc[mi][ni], al[mi], bh[ni]);
            }
        }
    }

    // ---- epilogue ----
#pragma unroll
    for (int mi = 0; mi < 4; ++mi) {
#pragma unroll
        for (int ni = 0; ni < 4; ++ni) {
            const int row = m0 + wm * 64 + mi * 16 + gid;
            const int col = n0 + wn * 32 + ni * 8 + 2 * tid;
            const float* a4 = acc[mi][ni];
            if (!EPI_T) {
                *(float2*)&C[(long)row * ldc + col] = make_float2(a4[0], a4[1]);
                *(float2*)&C[(long)(row + 8) * ldc + col] = make_float2(a4[2], a4[3]);
            } else {
                C[(long)col * ldc + row]           = a4[0];
                C[(long)(col + 1) * ldc + row]     = a4[1];
                C[(long)col * ldc + row + 8]       = a4[2];
                C[(long)(col + 1) * ldc + row + 8] = a4[3];
            }
        }
    }
}

// ---------------------------------------------------------------------------
// Transpose x[b][c][n] -> xT[b][n][c]
// ---------------------------------------------------------------------------
__global__ __launch_bounds__(256)
void transpose_x(const float* __restrict__ x, float* __restrict__ xt)
{
    __shared__ float tile[32][33];
    const float* xb = x + (long)blockIdx.z * C_IN * NTOK;
    float* xtb = xt + (long)blockIdx.z * NTOK * C_IN;
    const int n0 = blockIdx.x * 32, c0 = blockIdx.y * 32;
    const int tx = threadIdx.x & 31, ty = threadIdx.x >> 5;  // 32 x 8
#pragma unroll
    for (int i = ty; i < 32; i += 8)
        tile[i][tx] = xb[(long)(c0 + i) * NTOK + n0 + tx];
    __syncthreads();
#pragma unroll
    for (int i = ty; i < 32; i += 8)
        xtb[(long)(n0 + i) * C_IN + c0 + tx] = tile[tx][i];
}

// ---------------------------------------------------------------------------
// Column softmax over ST[b][j][i]: softmax along j for each column i, in place.
// Thread t owns column i; all row accesses are coalesced.
// ---------------------------------------------------------------------------
__global__ __launch_bounds__(256)
void softmax_col_kernel(float* __restrict__ S)
{
    float* p = S + (long)blockIdx.y * NTOK * NTOK + blockIdx.x * 256 + threadIdx.x;
    float mx = -CUDART_INF_F;
#pragma unroll 4
    for (int j = 0; j < NTOK; ++j) mx = fmaxf(mx, p[(long)j * NTOK]);
    float s = 0.f;
#pragma unroll 4
    for (int j = 0; j < NTOK; ++j) s += __expf(p[(long)j * NTOK] - mx);
    const float inv = 1.f / s;
#pragma unroll 4
    for (int j = 0; j < NTOK; ++j) {
        float v = p[(long)j * NTOK];
        p[(long)j * NTOK] = __expf(v - mx) * inv;
    }
}

// ---------------------------------------------------------------------------
// Launch
// ---------------------------------------------------------------------------
extern "C" void kernel_launch(void* const* d_in, const int* in_sizes, int n_in,
                              void* d_out, int out_size)
{
    const float* x  = nullptr;
    const float* Wq = nullptr;
    const float* Wk = nullptr;
    const float* Wv = nullptr;
    for (int i = 0; i < n_in; ++i) {
        const float* p = (const float*)d_in[i];
        if (in_sizes[i] == BATCH * C_IN * NTOK)      x = p;
        else if (in_sizes[i] == C_OUT * C_IN)        Wv = p;
        else if (in_sizes[i] == C_KEY * C_IN) {
            if (!Wq) Wq = p; else Wk = p;
        }
    }

    float *xt, *qt, *kt, *v, *s;
    cudaGetSymbolAddress((void**)&xt, g_xt);
    cudaGetSymbolAddress((void**)&qt, g_qt);
    cudaGetSymbolAddress((void**)&kt, g_kt);
    cudaGetSymbolAddress((void**)&v,  g_v);
    cudaGetSymbolAddress((void**)&s,  g_s);
    float* out = (float*)d_out;

    cudaFuncSetAttribute(tc_gemm<true,  true >, cudaFuncAttributeMaxDynamicSharedMemorySize, SMEM_SPLIT);
    cudaFuncSetAttribute(tc_gemm<true,  false>, cudaFuncAttributeMaxDynamicSharedMemorySize, SMEM_SPLIT);
    cudaFuncSetAttribute(tc_gemm<false, true >, cudaFuncAttributeMaxDynamicSharedMemorySize, SMEM_SINGLE);
    cudaFuncSetAttribute(tc_gemm<false, false>, cudaFuncAttributeMaxDynamicSharedMemorySize, SMEM_SINGLE);

    // 0) xT[b][n][c] = x[b][c][n]
    transpose_x<<<dim3(NTOK / 32, C_IN / 32, BATCH), 256>>>(x, xt);

    // 1) q/k projections (SPLIT, epilogue-T -> qT/kT[n][o], o contiguous)
    //    D[o,n] = sum_c Wq[o,c] * xT[n,c]
    tc_gemm<true, true><<<dim3(NTOK / 128, C_KEY / 128, BATCH), 256, SMEM_SPLIT>>>(
        Wq, xt, qt, C_IN, C_IN, C_IN, C_KEY,
        0L, (long)NTOK * C_IN, (long)NTOK * C_KEY);
    tc_gemm<true, true><<<dim3(NTOK / 128, C_KEY / 128, BATCH), 256, SMEM_SPLIT>>>(
        Wk, xt, kt, C_IN, C_IN, C_IN, C_KEY,
        0L, (long)NTOK * C_IN, (long)NTOK * C_KEY);

    // 2) v projection (single tf32, epilogue-N -> v[c][i], i contiguous)
    tc_gemm<false, false><<<dim3(NTOK / 128, C_OUT / 128, BATCH), 256, SMEM_SINGLE>>>(
        Wv, xt, v, C_IN, C_IN, C_IN, NTOK,
        0L, (long)NTOK * C_IN, (long)C_OUT * NTOK);

    // 3) sim, transposed: ST[j][i] = sum_c qT[j,c] * kT[i,c]  (SPLIT, epi-N)
    tc_gemm<true, false><<<dim3(NTOK / 128, NTOK / 128, BATCH), 256, SMEM_SPLIT>>>(
        qt, kt, s, C_KEY, C_KEY, C_KEY, NTOK,
        (long)NTOK * C_KEY, (long)NTOK * C_KEY, (long)NTOK * NTOK);

    // 4) column softmax over j (in place): ST -> attnT, attn[i][j] at s[j][i]
    softmax_col_kernel<<<dim3(NTOK / 256, BATCH), 256>>>(s);

    // 5) out: D[c,m] = sum_i v[c,i] * attnT[m,i]; epilogue-T -> out[m][c]
    tc_gemm<false, true><<<dim3(NTOK / 128, C_OUT / 128, BATCH), 256, SMEM_SINGLE>>>(
        v, s, out, NTOK, NTOK, NTOK, C_OUT,
        (long)C_OUT * NTOK, (long)NTOK * NTOK, (long)NTOK * C_OUT);
}

// round 13
// speedup vs baseline: 1.0123x; 1.0123x over previous
#include <cuda_runtime.h>
#include <math_constants.h>
#include <cstdint>

// Problem constants
#define BATCH 8
#define C_IN  512
#define C_OUT 512
#define C_KEY 256
#define NTOK  2048

// ---------------------------------------------------------------------------
// Scratch (__device__ globals; no cudaMalloc allowed)
// ---------------------------------------------------------------------------
__device__ float g_xt[BATCH * NTOK * C_IN];   // xT[b][n][c]
__device__ float g_qt[BATCH * NTOK * C_KEY];  // qT[b][n][ck]
__device__ float g_kt[BATCH * NTOK * C_KEY];  // kT[b][n][ck]
__device__ float g_v [BATCH * C_OUT * NTOK];  // v[b][c][i]  (i contiguous)
__device__ float g_s [BATCH * NTOK * NTOK];   // ST[b][j][i] -> attnT in place

// ---------------------------------------------------------------------------
// tf32 helpers (base-PTX features, valid on .target sm_103)
// ---------------------------------------------------------------------------
__device__ __forceinline__ uint32_t tf32_rna(float f) {
    uint32_t u;
    asm("cvt.rna.tf32.f32 %0, %1;" : "=r"(u) : "f"(f));
    return u;
}

__device__ __forceinline__ void mma_tf32(float* d, const uint32_t* a,
                                         const uint32_t* b)
{
    asm volatile(
        "mma.sync.aligned.m16n8k8.row.col.f32.tf32.tf32.f32 "
        "{%0,%1,%2,%3}, {%4,%5,%6,%7}, {%8,%9}, {%0,%1,%2,%3};"
        : "+f"(d[0]), "+f"(d[1]), "+f"(d[2]), "+f"(d[3])
        : "r"(a[0]), "r"(a[1]), "r"(a[2]), "r"(a[3]),
          "r"(b[0]), "r"(b[1]));
}

// ---------------------------------------------------------------------------
// Tensor-core tf32 GEMM:  D[m,n] = sum_k A[m,k] * B[n,k]  (both K-major)
// 128x128 CTA tile, BK=32, 256 threads (8 warps, each 64x32).
// SPLIT : 2xtf32 precision (hi/lo, 3 MMA passes).
// EPI_T : store C[n][m] instead of C[m][n].
// smem tile layout: row-major [128][36] floats (stride 36 => conflict-free
// fragment LDS.32 and conflict-free float4 STS).
// ---------------------------------------------------------------------------
#define LDK 36
#define TILE_F (128 * LDK)                  // floats per tile
#define SMEM_SINGLE (2 * TILE_F * 4)        // 36864 B
#define SMEM_SPLIT  (4 * TILE_F * 4)        // 73728 B

template <bool SPLIT, bool EPI_T>
__global__ __launch_bounds__(256)
void tc_gemm(const float* __restrict__ A, const float* __restrict__ B,
             float* __restrict__ C,
             int K, int lda, int ldb, int ldc,
             long sA, long sB, long sC)
{
    extern __shared__ float sm[];
    float* Ah = sm;
    float* Bh = sm + TILE_F;
    float* Al = sm + 2 * TILE_F;   // SPLIT only
    float* Bl = sm + 3 * TILE_F;   // SPLIT only

    const int t   = threadIdx.x;
    const int l   = t & 31;
    const int w   = t >> 5;
    const int gid = l >> 2;        // 0..7
    const int tid = l & 3;         // 0..3
    const int wm  = w >> 2;        // 0..1 -> m offset wm*64
    const int wn  = w & 3;         // 0..3 -> n offset wn*32

    A += (long)blockIdx.z * sA;
    B += (long)blockIdx.z * sB;
    C += (long)blockIdx.z * sC;
    const int m0 = blockIdx.y * 128;
    const int n0 = blockIdx.x * 128;

    // loader lanes: 8 lanes cover one row's 32 floats (coalesced 128B)
    const int lr = t >> 3;         // 0..31
    const int lc = (t & 7) * 4;    // 0,4,...,28

    float acc[4][4][4];
#pragma unroll
    for (int mi = 0; mi < 4; ++mi)
#pragma unroll
        for (int ni = 0; ni < 4; ++ni)
#pragma unroll
            for (int c = 0; c < 4; ++c) acc[mi][ni][c] = 0.f;

#pragma unroll 1
    for (int k0 = 0; k0 < K; k0 += 32) {
        __syncthreads();   // previous compute done before overwrite

        // ---- global -> smem (convert to tf32, optional hi/lo split) ----
#pragma unroll
        for (int p = 0; p < 4; ++p) {
            const int r = lr + p * 32;
            // A tile
            {
                float4 v = *(const float4*)(A + (long)(m0 + r) * lda + k0 + lc);
                uint4 h;
                h.x = tf32_rna(v.x); h.y = tf32_rna(v.y);
                h.z = tf32_rna(v.z); h.w = tf32_rna(v.w);
                *(uint4*)&Ah[r * LDK + lc] = h;
                if (SPLIT) {
                    uint4 lo;
                    lo.x = tf32_rna(v.x - __uint_as_float(h.x));
                    lo.y = tf32_rna(v.y - __uint_as_float(h.y));
                    lo.z = tf32_rna(v.z - __uint_as_float(h.z));
                    lo.w = tf32_rna(v.w - __uint_as_float(h.w));
                    *(uint4*)&Al[r * LDK + lc] = lo;
                }
            }
            // B tile
            {
                float4 v = *(const float4*)(B + (long)(n0 + r) * ldb + k0 + lc);
                uint4 h;
                h.x = tf32_rna(v.x); h.y = tf32_rna(v.y);
                h.z = tf32_rna(v.z); h.w = tf32_rna(v.w);
                *(uint4*)&Bh[r * LDK + lc] = h;
                if (SPLIT) {
                    uint4 lo;
                    lo.x = tf32_rna(v.x - __uint_as_float(h.x));
                    lo.y = tf32_rna(v.y - __uint_as_float(h.y));
                    lo.z = tf32_rna(v.z - __uint_as_float(h.z));
                    lo.w = tf32_rna(v.w - __uint_as_float(h.w));
                    *(uint4*)&Bl[r * LDK + lc] = lo;
                }
            }
        }
        __syncthreads();

        // ---- compute: 4 k-steps of 8 ----
#pragma unroll
        for (int s = 0; s < 4; ++s) {
            const int ks = s * 8;

            uint32_t bh[4][2];
#pragma unroll
            for (int ni = 0; ni < 4; ++ni) {
                const float* bp = &Bh[(wn * 32 + ni * 8 + gid) * LDK + ks + tid];
                bh[ni][0] = __float_as_uint(bp[0]);
                bh[ni][1] = __float_as_uint(bp[4]);
            }
            uint32_t ah[4][4];
#pragma unroll
            for (int mi = 0; mi < 4; ++mi) {
                const float* ap = &Ah[(wm * 64 + mi * 16 + gid) * LDK + ks + tid];
                ah[mi][0] = __float_as_uint(ap[0]);
                ah[mi][1] = __float_as_uint(ap[8 * LDK]);
                ah[mi][2] = __float_as_uint(ap[4]);
                ah[mi][3] = __float_as_uint(ap[8 * LDK + 4]);
            }
#pragma unroll
            for (int mi = 0; mi < 4; ++mi)
#pragma unroll
                for (int ni = 0; ni < 4; ++ni)
                    mma_tf32(acc[mi][ni], ah[mi], bh[ni]);

            if (SPLIT) {
                uint32_t bl[4][2];
#pragma unroll
                for (int ni = 0; ni < 4; ++ni) {
                    const float* bp = &Bl[(wn * 32 + ni * 8 + gid) * LDK + ks + tid];
                    bl[ni][0] = __float_as_uint(bp[0]);
                    bl[ni][1] = __float_as_uint(bp[4]);
                }
#pragma unroll
                for (int mi = 0; mi < 4; ++mi)
#pragma unroll
                    for (int ni = 0; ni < 4; ++ni)
                        mma_tf32(acc[mi][ni], ah[mi], bl[ni]);

                uint32_t al[4][4];
#pragma unroll
                for (int mi = 0; mi < 4; ++mi) {
                    const float* ap = &Al[(wm * 64 + mi * 16 + gid) * LDK + ks + tid];
                    al[mi][0] = __float_as_uint(ap[0]);
                    al[mi][1] = __float_as_uint(ap[8 * LDK]);
                    al[mi][2] = __float_as_uint(ap[4]);
                    al[mi][3] = __float_as_uint(ap[8 * LDK + 4]);
                }
#pragma unroll
                for (int mi = 0; mi < 4; ++mi)
#pragma unroll
                    for (int ni = 0; ni < 4; ++ni)
                        mma_tf32(acc[mi][ni], al[mi], bh[ni]);
            }
        }
    }

    // ---- epilogue ----
#pragma unroll
    for (int mi = 0; mi < 4; ++mi) {
#pragma unroll
        for (int ni = 0; ni < 4; ++ni) {
            const int row = m0 + wm * 64 + mi * 16 + gid;
            const int col = n0 + wn * 32 + ni * 8 + 2 * tid;
            const float* a4 = acc[mi][ni];
            if (!EPI_T) {
                *(float2*)&C[(long)row * ldc + col] = make_float2(a4[0], a4[1]);
                *(float2*)&C[(long)(row + 8) * ldc + col] = make_float2(a4[2], a4[3]);
            } else {
                C[(long)col * ldc + row]           = a4[0];
                C[(long)(col + 1) * ldc + row]     = a4[1];
                C[(long)col * ldc + row + 8]       = a4[2];
                C[(long)(col + 1) * ldc + row + 8] = a4[3];
            }
        }
    }
}

// ---------------------------------------------------------------------------
// Transpose x[b][c][n] -> xT[b][n][c]
// ---------------------------------------------------------------------------
__global__ __launch_bounds__(256)
void transpose_x(const float* __restrict__ x, float* __restrict__ xt)
{
    __shared__ float tile[32][33];
    const float* xb = x + (long)blockIdx.z * C_IN * NTOK;
    float* xtb = xt + (long)blockIdx.z * NTOK * C_IN;
    const int n0 = blockIdx.x * 32, c0 = blockIdx.y * 32;
    const int tx = threadIdx.x & 31, ty = threadIdx.x >> 5;  // 32 x 8
#pragma unroll
    for (int i = ty; i < 32; i += 8)
        tile[i][tx] = xb[(long)(c0 + i) * NTOK + n0 + tx];
    __syncthreads();
#pragma unroll
    for (int i = ty; i < 32; i += 8)
        xtb[(long)(n0 + i) * C_IN + c0 + tx] = tile[tx][i];
}

// ---------------------------------------------------------------------------
// Column softmax over ST[b][j][i]: softmax along j for each column i, in place.
// Thread t owns column i; all row accesses are coalesced.
// ---------------------------------------------------------------------------
__global__ __launch_bounds__(256)
void softmax_col_kernel(float* __restrict__ S)
{
    float* p = S + (long)blockIdx.y * NTOK * NTOK + blockIdx.x * 256 + threadIdx.x;
    float mx = -CUDART_INF_F;
#pragma unroll 4
    for (int j = 0; j < NTOK; ++j) mx = fmaxf(mx, p[(long)j * NTOK]);
    float s = 0.f;
#pragma unroll 4
    for (int j = 0; j < NTOK; ++j) s += __expf(p[(long)j * NTOK] - mx);
    const float inv = 1.f / s;
#pragma unroll 4
    for (int j = 0; j < NTOK; ++j) {
        float v = p[(long)j * NTOK];
        p[(long)j * NTOK] = __expf(v - mx) * inv;
    }
}

// ---------------------------------------------------------------------------
// Launch
// ---------------------------------------------------------------------------
extern "C" void kernel_launch(void* const* d_in, const int* in_sizes, int n_in,
                              void* d_out, int out_size)
{
    const float* x  = nullptr;
    const float* Wq = nullptr;
    const float* Wk = nullptr;
    const float* Wv = nullptr;
    for (int i = 0; i < n_in; ++i) {
        const float* p = (const float*)d_in[i];
        if (in_sizes[i] == BATCH * C_IN * NTOK)      x = p;
        else if (in_sizes[i] == C_OUT * C_IN)        Wv = p;
        else if (in_sizes[i] == C_KEY * C_IN) {
            if (!Wq) Wq = p; else Wk = p;
        }
    }

    float *xt, *qt, *kt, *v, *s;
    cudaGetSymbolAddress((void**)&xt, g_xt);
    cudaGetSymbolAddress((void**)&qt, g_qt);
    cudaGetSymbolAddress((void**)&kt, g_kt);
    cudaGetSymbolAddress((void**)&v,  g_v);
    cudaGetSymbolAddress((void**)&s,  g_s);
    float* out = (float*)d_out;

    cudaFuncSetAttribute(tc_gemm<true,  true >, cudaFuncAttributeMaxDynamicSharedMemorySize, SMEM_SPLIT);
    cudaFuncSetAttribute(tc_gemm<true,  false>, cudaFuncAttributeMaxDynamicSharedMemorySize, SMEM_SPLIT);
    cudaFuncSetAttribute(tc_gemm<false, true >, cudaFuncAttributeMaxDynamicSharedMemorySize, SMEM_SINGLE);
    cudaFuncSetAttribute(tc_gemm<false, false>, cudaFuncAttributeMaxDynamicSharedMemorySize, SMEM_SINGLE);

    // 0) xT[b][n][c] = x[b][c][n]
    transpose_x<<<dim3(NTOK / 32, C_IN / 32, BATCH), 256>>>(x, xt);

    // 1) q/k projections (SPLIT, epilogue-T -> qT/kT[n][o], o contiguous)
    //    D[o,n] = sum_c Wq[o,c] * xT[n,c]
    tc_gemm<true, true><<<dim3(NTOK / 128, C_KEY / 128, BATCH), 256, SMEM_SPLIT>>>(
        Wq, xt, qt, C_IN, C_IN, C_IN, C_KEY,
        0L, (long)NTOK * C_IN, (long)NTOK * C_KEY);
    tc_gemm<true, true><<<dim3(NTOK / 128, C_KEY / 128, BATCH), 256, SMEM_SPLIT>>>(
        Wk, xt, kt, C_IN, C_IN, C_IN, C_KEY,
        0L, (long)NTOK * C_IN, (long)NTOK * C_KEY);

    // 2) v projection (single tf32, epilogue-N -> v[c][i], i contiguous)
    tc_gemm<false, false><<<dim3(NTOK / 128, C_OUT / 128, BATCH), 256, SMEM_SINGLE>>>(
        Wv, xt, v, C_IN, C_IN, C_IN, NTOK,
        0L, (long)NTOK * C_IN, (long)C_OUT * NTOK);

    // 3) sim, transposed: ST[j][i] = sum_c qT[j,c] * kT[i,c]  (SPLIT, epi-N)
    tc_gemm<true, false><<<dim3(NTOK / 128, NTOK / 128, BATCH), 256, SMEM_SPLIT>>>(
        qt, kt, s, C_KEY, C_KEY, C_KEY, NTOK,
        (long)NTOK * C_KEY, (long)NTOK * C_KEY, (long)NTOK * NTOK);

    // 4) column softmax over j (in place): ST -> attnT, attn[i][j] at s[j][i]
    softmax_col_kernel<<<dim3(NTOK / 256, BATCH), 256>>>(s);

    // 5) out: D[c,m] = sum_i v[c,i] * attnT[m,i]; epilogue-T -> out[m][c]
    tc_gemm<false, true><<<dim3(NTOK / 128, C_OUT / 128, BATCH), 256, SMEM_SINGLE>>>(
        v, s, out, NTOK, NTOK, NTOK, C_OUT,
        (long)C_OUT * NTOK, (long)NTOK * NTOK, (long)NTOK * C_OUT);
}

// round 14
// speedup vs baseline: 1.0575x; 1.0446x over previous
#include <cuda_runtime.h>
#include <math_constants.h>
#include <cstdint>

// Problem constants
#define BATCH 8
#define C_IN  512
#define C_OUT 512
#define C_KEY 256
#define NTOK  2048

// ---------------------------------------------------------------------------
// Scratch (__device__ globals; no cudaMalloc allowed)
// ---------------------------------------------------------------------------
__device__ float g_xt[BATCH * NTOK * C_IN];   // xT[b][n][c]
__device__ float g_qt[BATCH * NTOK * C_KEY];  // qT[b][n][ck]
__device__ float g_kt[BATCH * NTOK * C_KEY];  // kT[b][n][ck]
__device__ float g_v [BATCH * C_OUT * NTOK];  // v[b][c][i]  (i contiguous)
__device__ float g_s [BATCH * NTOK * NTOK];   // ST[b][j][i] -> attnT in place

// ---------------------------------------------------------------------------
// Base-PTX helpers (valid on .target sm_103 — no tcgen05)
// ---------------------------------------------------------------------------
__device__ __forceinline__ uint32_t tf32_rna(float f) {
    uint32_t u;
    asm("cvt.rna.tf32.f32 %0, %1;" : "=r"(u) : "f"(f));
    return u;
}

__device__ __forceinline__ void mma_tf32(float* d, const uint32_t* a,
                                         const uint32_t* b)
{
    asm volatile(
        "mma.sync.aligned.m16n8k8.row.col.f32.tf32.tf32.f32 "
        "{%0,%1,%2,%3}, {%4,%5,%6,%7}, {%8,%9}, {%0,%1,%2,%3};"
        : "+f"(d[0]), "+f"(d[1]), "+f"(d[2]), "+f"(d[3])
        : "r"(a[0]), "r"(a[1]), "r"(a[2]), "r"(a[3]),
          "r"(b[0]), "r"(b[1]));
}

__device__ __forceinline__ uint32_t smem_to_u32(const void* p) {
    uint32_t a;
    asm("{ .reg .u64 t; cvta.to.shared.u64 t, %1; cvt.u32.u64 %0, t; }"
        : "=r"(a) : "l"(p));
    return a;
}
__device__ __forceinline__ void cp16(uint32_t dst, const float* src) {
    asm volatile("cp.async.cg.shared.global [%0], [%1], 16;"
                 :: "r"(dst), "l"(src));
}
#define CP_COMMIT() asm volatile("cp.async.commit_group;" ::: "memory")
#define CP_WAIT2()  asm volatile("cp.async.wait_group 2;" ::: "memory")

// ---------------------------------------------------------------------------
// Pipelined tensor-core tf32 GEMM:  D[m,n] = sum_k A[m,k] * B[n,k] (K-major)
// 128x128 CTA tile, BK=32, 256 threads (8 warps, 64x32 warp tile).
// 3-stage cp.async pipeline of RAW fp32 tiles; tf32 conversion (and hi/lo
// split) happens at fragment-load time in registers.
// SPLIT : 2xtf32 precision (3 MMA passes).  EPI_T : store C[n][m].
// smem: [STAGES][A|B][128][36] floats (stride 36 -> conflict-free LDS/STS).
// ---------------------------------------------------------------------------
#define LDK 36
#define TILE_F (128 * LDK)                    // 4608 floats / 18432 B
#define STAGES 3
#define SMEM_BYTES (STAGES * 2 * TILE_F * 4)  // 110592 B

template <bool SPLIT, bool EPI_T>
__global__ __launch_bounds__(256)
void tc_gemm(const float* __restrict__ A, const float* __restrict__ B,
             float* __restrict__ C,
             int K, int lda, int ldb, int ldc,
             long sA, long sB, long sC)
{
    extern __shared__ float smx[];
    const uint32_t sbase = smem_to_u32(smx);

    const int t   = threadIdx.x;
    const int l   = t & 31;
    const int w   = t >> 5;
    const int gid = l >> 2;        // 0..7
    const int tid = l & 3;         // 0..3
    const int wm  = w >> 2;        // 0..1 -> m offset wm*64
    const int wn  = w & 3;         // 0..3 -> n offset wn*32

    A += (long)blockIdx.z * sA;
    B += (long)blockIdx.z * sB;
    C += (long)blockIdx.z * sC;
    const int m0 = blockIdx.y * 128;
    const int n0 = blockIdx.x * 128;

    // loader lanes: 8 lanes cover one row's 32 floats (128B, coalesced)
    const int lr = t >> 3;         // 0..31
    const int lc = (t & 7) * 4;    // 0,4,...,28

    const int nt = K / 32;

    auto load_stage = [&](int stg, int k0) {
        const uint32_t ab = sbase + (uint32_t)stg * (2 * TILE_F * 4);
        const uint32_t bb = ab + TILE_F * 4;
#pragma unroll
        for (int p = 0; p < 4; ++p) {
            const int r = lr + p * 32;
            const uint32_t so = (uint32_t)(r * LDK + lc) * 4;
            cp16(ab + so, A + (long)(m0 + r) * lda + k0 + lc);
            cp16(bb + so, B + (long)(n0 + r) * ldb + k0 + lc);
        }
    };

    float acc[4][4][4];
#pragma unroll
    for (int mi = 0; mi < 4; ++mi)
#pragma unroll
        for (int ni = 0; ni < 4; ++ni)
#pragma unroll
            for (int c = 0; c < 4; ++c) acc[mi][ni][c] = 0.f;

    // prologue: fill the pipeline
    load_stage(0, 0); CP_COMMIT();
    if (nt > 1) load_stage(1, 32);
    CP_COMMIT();
    if (nt > 2) load_stage(2, 64);
    CP_COMMIT();

    int stg = 0;
#pragma unroll 1
    for (int tt = 0; tt < nt; ++tt) {
        CP_WAIT2();            // stage `stg` complete
        __syncthreads();

        const float* Ar = smx + stg * 2 * TILE_F;
        const float* Br = Ar + TILE_F;

        // ---- compute: 4 k-steps of 8 ----
#pragma unroll
        for (int s = 0; s < 4; ++s) {
            const int ks = s * 8;

            uint32_t bh[4][2], bl[4][2];
#pragma unroll
            for (int ni = 0; ni < 4; ++ni) {
                const float* bp = &Br[(wn * 32 + ni * 8 + gid) * LDK + ks + tid];
                const float r0 = bp[0], r1 = bp[4];
                bh[ni][0] = tf32_rna(r0);
                bh[ni][1] = tf32_rna(r1);
                if (SPLIT) {
                    bl[ni][0] = tf32_rna(r0 - __uint_as_float(bh[ni][0]));
                    bl[ni][1] = tf32_rna(r1 - __uint_as_float(bh[ni][1]));
                }
            }
            uint32_t ah[4][4], al[4][4];
#pragma unroll
            for (int mi = 0; mi < 4; ++mi) {
                const float* ap = &Ar[(wm * 64 + mi * 16 + gid) * LDK + ks + tid];
                const float r0 = ap[0], r1 = ap[8 * LDK];
                const float r2 = ap[4], r3 = ap[8 * LDK + 4];
                ah[mi][0] = tf32_rna(r0);
                ah[mi][1] = tf32_rna(r1);
                ah[mi][2] = tf32_rna(r2);
                ah[mi][3] = tf32_rna(r3);
                if (SPLIT) {
                    al[mi][0] = tf32_rna(r0 - __uint_as_float(ah[mi][0]));
                    al[mi][1] = tf32_rna(r1 - __uint_as_float(ah[mi][1]));
                    al[mi][2] = tf32_rna(r2 - __uint_as_float(ah[mi][2]));
                    al[mi][3] = tf32_rna(r3 - __uint_as_float(ah[mi][3]));
                }
            }

#pragma unroll
            for (int mi = 0; mi < 4; ++mi)
#pragma unroll
                for (int ni = 0; ni < 4; ++ni)
                    mma_tf32(acc[mi][ni], ah[mi], bh[ni]);
            if (SPLIT) {
#pragma unroll
                for (int mi = 0; mi < 4; ++mi)
#pragma unroll
                    for (int ni = 0; ni < 4; ++ni)
                        mma_tf32(acc[mi][ni], ah[mi], bl[ni]);
#pragma unroll
                for (int mi = 0; mi < 4; ++mi)
#pragma unroll
                    for (int ni = 0; ni < 4; ++ni)
                        mma_tf32(acc[mi][ni], al[mi], bh[ni]);
            }
        }

        __syncthreads();       // all warps done with stage before refill
        if (tt + STAGES < nt) load_stage(stg, (tt + STAGES) * 32);
        CP_COMMIT();           // keep group FIFO accounting uniform
        stg = (stg == STAGES - 1) ? 0 : stg + 1;
    }

    // ---- epilogue ----
#pragma unroll
    for (int mi = 0; mi < 4; ++mi) {
#pragma unroll
        for (int ni = 0; ni < 4; ++ni) {
            const int row = m0 + wm * 64 + mi * 16 + gid;
            const int col = n0 + wn * 32 + ni * 8 + 2 * tid;
            const float* a4 = acc[mi][ni];
            if (!EPI_T) {
                *(float2*)&C[(long)row * ldc + col] = make_float2(a4[0], a4[1]);
                *(float2*)&C[(long)(row + 8) * ldc + col] = make_float2(a4[2], a4[3]);
            } else {
                C[(long)col * ldc + row]           = a4[0];
                C[(long)(col + 1) * ldc + row]     = a4[1];
                C[(long)col * ldc + row + 8]       = a4[2];
                C[(long)(col + 1) * ldc + row + 8] = a4[3];
            }
        }
    }
}

// ---------------------------------------------------------------------------
// Transpose x[b][c][n] -> xT[b][n][c]
// ---------------------------------------------------------------------------
__global__ __launch_bounds__(256)
void transpose_x(const float* __restrict__ x, float* __restrict__ xt)
{
    __shared__ float tile[32][33];
    const float* xb = x + (long)blockIdx.z * C_IN * NTOK;
    float* xtb = xt + (long)blockIdx.z * NTOK * C_IN;
    const int n0 = blockIdx.x * 32, c0 = blockIdx.y * 32;
    const int tx = threadIdx.x & 31, ty = threadIdx.x >> 5;  // 32 x 8
#pragma unroll
    for (int i = ty; i < 32; i += 8)
        tile[i][tx] = xb[(long)(c0 + i) * NTOK + n0 + tx];
    __syncthreads();
#pragma unroll
    for (int i = ty; i < 32; i += 8)
        xtb[(long)(n0 + i) * C_IN + c0 + tx] = tile[tx][i];
}

// ---------------------------------------------------------------------------
// Column softmax over ST[b][j][i] along j, in place. Online max+sum (1 read)
// then normalize pass (1 read + 1 write). Each thread owns 4 adjacent
// columns -> float4 coalesced rows + 4-wide ILP on the serial chain.
// ---------------------------------------------------------------------------
__global__ __launch_bounds__(256)
void softmax_col_kernel(float* __restrict__ S)
{
    float* p = S + (long)blockIdx.y * NTOK * NTOK
                 + (blockIdx.x * 256 + threadIdx.x) * 4;

    float4 m = make_float4(-CUDART_INF_F, -CUDART_INF_F,
                           -CUDART_INF_F, -CUDART_INF_F);
    float4 s = make_float4(0.f, 0.f, 0.f, 0.f);
#pragma unroll 4
    for (int j = 0; j < NTOK; ++j) {
        const float4 v = *(const float4*)&p[(long)j * NTOK];
        float4 mn;
        mn.x = fmaxf(m.x, v.x); mn.y = fmaxf(m.y, v.y);
        mn.z = fmaxf(m.z, v.z); mn.w = fmaxf(m.w, v.w);
        s.x = s.x * __expf(m.x - mn.x) + __expf(v.x - mn.x);
        s.y = s.y * __expf(m.y - mn.y) + __expf(v.y - mn.y);
        s.z = s.z * __expf(m.z - mn.z) + __expf(v.z - mn.z);
        s.w = s.w * __expf(m.w - mn.w) + __expf(v.w - mn.w);
        m = mn;
    }
    const float4 inv = make_float4(1.f / s.x, 1.f / s.y, 1.f / s.z, 1.f / s.w);
#pragma unroll 4
    for (int j = 0; j < NTOK; ++j) {
        float4 v = *(const float4*)&p[(long)j * NTOK];
        v.x = __expf(v.x - m.x) * inv.x;
        v.y = __expf(v.y - m.y) * inv.y;
        v.z = __expf(v.z - m.z) * inv.z;
        v.w = __expf(v.w - m.w) * inv.w;
        *(float4*)&p[(long)j * NTOK] = v;
    }
}

// ---------------------------------------------------------------------------
// Launch
// ---------------------------------------------------------------------------
extern "C" void kernel_launch(void* const* d_in, const int* in_sizes, int n_in,
                              void* d_out, int out_size)
{
    const float* x  = nullptr;
    const float* Wq = nullptr;
    const float* Wk = nullptr;
    const float* Wv = nullptr;
    for (int i = 0; i < n_in; ++i) {
        const float* p = (const float*)d_in[i];
        if (in_sizes[i] == BATCH * C_IN * NTOK)      x = p;
        else if (in_sizes[i] == C_OUT * C_IN)        Wv = p;
        else if (in_sizes[i] == C_KEY * C_IN) {
            if (!Wq) Wq = p; else Wk = p;
        }
    }

    float *xt, *qt, *kt, *v, *s;
    cudaGetSymbolAddress((void**)&xt, g_xt);
    cudaGetSymbolAddress((void**)&qt, g_qt);
    cudaGetSymbolAddress((void**)&kt, g_kt);
    cudaGetSymbolAddress((void**)&v,  g_v);
    cudaGetSymbolAddress((void**)&s,  g_s);
    float* out = (float*)d_out;

    cudaFuncSetAttribute(tc_gemm<true,  true >, cudaFuncAttributeMaxDynamicSharedMemorySize, SMEM_BYTES);
    cudaFuncSetAttribute(tc_gemm<true,  false>, cudaFuncAttributeMaxDynamicSharedMemorySize, SMEM_BYTES);
    cudaFuncSetAttribute(tc_gemm<false, true >, cudaFuncAttributeMaxDynamicSharedMemorySize, SMEM_BYTES);
    cudaFuncSetAttribute(tc_gemm<false, false>, cudaFuncAttributeMaxDynamicSharedMemorySize, SMEM_BYTES);

    // 0) xT[b][n][c] = x[b][c][n]
    transpose_x<<<dim3(NTOK / 32, C_IN / 32, BATCH), 256>>>(x, xt);

    // 1) q/k projections (SPLIT, epilogue-T -> qT/kT[n][o], o contiguous)
    tc_gemm<true, true><<<dim3(NTOK / 128, C_KEY / 128, BATCH), 256, SMEM_BYTES>>>(
        Wq, xt, qt, C_IN, C_IN, C_IN, C_KEY,
        0L, (long)NTOK * C_IN, (long)NTOK * C_KEY);
    tc_gemm<true, true><<<dim3(NTOK / 128, C_KEY / 128, BATCH), 256, SMEM_BYTES>>>(
        Wk, xt, kt, C_IN, C_IN, C_IN, C_KEY,
        0L, (long)NTOK * C_IN, (long)NTOK * C_KEY);

    // 2) v projection (single tf32, epilogue-N -> v[c][i], i contiguous)
    tc_gemm<false, false><<<dim3(NTOK / 128, C_OUT / 128, BATCH), 256, SMEM_BYTES>>>(
        Wv, xt, v, C_IN, C_IN, C_IN, NTOK,
        0L, (long)NTOK * C_IN, (long)C_OUT * NTOK);

    // 3) sim, transposed: ST[j][i] = sum_c qT[j,c] * kT[i,c]  (SPLIT, epi-N)
    tc_gemm<true, false><<<dim3(NTOK / 128, NTOK / 128, BATCH), 256, SMEM_BYTES>>>(
        qt, kt, s, C_KEY, C_KEY, C_KEY, NTOK,
        (long)NTOK * C_KEY, (long)NTOK * C_KEY, (long)NTOK * NTOK);

    // 4) column softmax over j (in place): ST -> attnT, attn[i][j] at s[j][i]
    softmax_col_kernel<<<dim3(NTOK / 1024, BATCH), 256>>>(s);

    // 5) out: D[c,m] = sum_i v[c,i] * attnT[m,i]; epilogue-T -> out[m][c]
    tc_gemm<false, true><<<dim3(NTOK / 128, C_OUT / 128, BATCH), 256, SMEM_BYTES>>>(
        v, s, out, NTOK, NTOK, NTOK, C_OUT,
        (long)C_OUT * NTOK, (long)NTOK * NTOK, (long)NTOK * C_OUT);
}

// round 15
// speedup vs baseline: 2.5482x; 2.4097x over previous
#include <cuda_runtime.h>
#include <cuda_fp16.h>
#include <math_constants.h>
#include <cstdint>

// Problem constants
#define BATCH 8
#define C_IN  512
#define C_OUT 512
#define C_KEY 256
#define NTOK  2048

// ---------------------------------------------------------------------------
// Scratch (__device__ globals; no cudaMalloc allowed)
// ---------------------------------------------------------------------------
__device__ float g_xt[BATCH * NTOK * C_IN];   // xT[b][n][c]
__device__ float g_qt[BATCH * NTOK * C_KEY];  // qT[b][n][ck]
__device__ float g_kt[BATCH * NTOK * C_KEY];  // kT[b][n][ck]
__device__ float g_v [BATCH * C_OUT * NTOK];  // v[b][c][i]  (i contiguous)
__device__ float g_s [BATCH * NTOK * NTOK];   // ST[b][j][i] -> attnT in place

#define RS 16                                  // softmax row-split
__device__ float g_pm[BATCH * RS * NTOK];      // partial max
__device__ float g_ps[BATCH * RS * NTOK];      // partial sum

// ---------------------------------------------------------------------------
// Base-PTX helpers (valid on .target sm_103 — no tcgen05)
// ---------------------------------------------------------------------------
__device__ __forceinline__ uint32_t tf32_rna(float f) {
    uint32_t u;
    asm("cvt.rna.tf32.f32 %0, %1;" : "=r"(u) : "f"(f));
    return u;
}

__device__ __forceinline__ void mma_tf32(float* d, const uint32_t* a,
                                         const uint32_t* b)
{
    asm volatile(
        "mma.sync.aligned.m16n8k8.row.col.f32.tf32.tf32.f32 "
        "{%0,%1,%2,%3}, {%4,%5,%6,%7}, {%8,%9}, {%0,%1,%2,%3};"
        : "+f"(d[0]), "+f"(d[1]), "+f"(d[2]), "+f"(d[3])
        : "r"(a[0]), "r"(a[1]), "r"(a[2]), "r"(a[3]),
          "r"(b[0]), "r"(b[1]));
}

__device__ __forceinline__ void mma_f16(float* d, const uint32_t* a,
                                        const uint32_t* b)
{
    asm volatile(
        "mma.sync.aligned.m16n8k16.row.col.f32.f16.f16.f32 "
        "{%0,%1,%2,%3}, {%4,%5,%6,%7}, {%8,%9}, {%0,%1,%2,%3};"
        : "+f"(d[0]), "+f"(d[1]), "+f"(d[2]), "+f"(d[3])
        : "r"(a[0]), "r"(a[1]), "r"(a[2]), "r"(a[3]),
          "r"(b[0]), "r"(b[1]));
}

__device__ __forceinline__ uint32_t smem_to_u32(const void* p) {
    uint32_t a;
    asm("{ .reg .u64 t; cvta.to.shared.u64 t, %1; cvt.u32.u64 %0, t; }"
        : "=r"(a) : "l"(p));
    return a;
}
__device__ __forceinline__ void cp16(uint32_t dst, const float* src) {
    asm volatile("cp.async.cg.shared.global [%0], [%1], 16;"
                 :: "r"(dst), "l"(src));
}
#define CP_COMMIT() asm volatile("cp.async.commit_group;" ::: "memory")
#define CP_WAIT2()  asm volatile("cp.async.wait_group 2;" ::: "memory")

// ===========================================================================
// fp16-split GEMM (for q/k projections and sim):
//   D[m,n] = sum_k A[m,k] * B[n,k]   (both K-major fp32 inputs)
// hi = rn_f16(x*scale), lo = rn_f16(x*scale - hi); 3 MMA passes
// (hh, lo_a*hi_b, hi_a*lo_b) => product error ~2^-24. Power-of-2 pre-scales
// (SA=1024 on A, SB=256 on B) keep lo out of fp16-subnormal territory;
// epilogue multiplies by 2^-18 exactly.
// CTA 128x128, BK=32, 256 thr, 8 warps of 64x32. m16n8k16.
// smem: 4 static tiles [128][40] halfs (stride 40h = 20 words: fragment
// word pattern gid*20+tid covers all 32 banks conflict-free).
// ===========================================================================
#define HLDK 40
#define HTILE2 (128 * HLDK / 2)      // half2 per tile = 2560 (10240 B)
#define SA_SCALE 1024.0f
#define SB_SCALE 256.0f
#define DESCALE  (1.0f / (1024.0f * 256.0f))

template <bool EPI_T>
__global__ __launch_bounds__(256, 2)
void hp_gemm(const float* __restrict__ A, const float* __restrict__ B,
             float* __restrict__ C,
             int K, int lda, int ldb, int ldc,
             long sA, long sB, long sC)
{
    __shared__ __align__(16) __half2 AH[HTILE2];
    __shared__ __align__(16) __half2 AL[HTILE2];
    __shared__ __align__(16) __half2 BH[HTILE2];
    __shared__ __align__(16) __half2 BL[HTILE2];

    const int t   = threadIdx.x;
    const int l   = t & 31;
    const int w   = t >> 5;
    const int gid = l >> 2;
    const int tid = l & 3;
    const int wm  = w >> 2;        // 0..1 -> m offset wm*64
    const int wn  = w & 3;         // 0..3 -> n offset wn*32

    A += (long)blockIdx.z * sA;
    B += (long)blockIdx.z * sB;
    C += (long)blockIdx.z * sC;
    const int m0 = blockIdx.y * 128;
    const int n0 = blockIdx.x * 128;

    const int lr  = t >> 3;        // 0..31
    const int lc4 = (t & 7) * 4;   // 0..28

    float acc[4][4][4];
#pragma unroll
    for (int mi = 0; mi < 4; ++mi)
#pragma unroll
        for (int ni = 0; ni < 4; ++ni)
#pragma unroll
            for (int c = 0; c < 4; ++c) acc[mi][ni][c] = 0.f;

    const int nt = K / 32;
#pragma unroll 1
    for (int tt = 0; tt < nt; ++tt) {
        const int k0 = tt * 32;
        __syncthreads();    // previous compute done before overwrite

        // ---- loader: fp32 -> scaled fp16 hi/lo into smem ----
#pragma unroll
        for (int p = 0; p < 4; ++p) {
            const int r  = lr + p * 32;
            const int i2 = r * (HLDK / 2) + (t & 7) * 2;
            {
                float4 v = *(const float4*)(A + (long)(m0 + r) * lda + k0 + lc4);
                v.x *= SA_SCALE; v.y *= SA_SCALE; v.z *= SA_SCALE; v.w *= SA_SCALE;
                __half2 h0 = __float22half2_rn(make_float2(v.x, v.y));
                __half2 h1 = __float22half2_rn(make_float2(v.z, v.w));
                float2 f0 = __half22float2(h0), f1 = __half22float2(h1);
                __half2 l0 = __float22half2_rn(make_float2(v.x - f0.x, v.y - f0.y));
                __half2 l1 = __float22half2_rn(make_float2(v.z - f1.x, v.w - f1.y));
                AH[i2] = h0; AH[i2 + 1] = h1;
                AL[i2] = l0; AL[i2 + 1] = l1;
            }
            {
                float4 v = *(const float4*)(B + (long)(n0 + r) * ldb + k0 + lc4);
                v.x *= SB_SCALE; v.y *= SB_SCALE; v.z *= SB_SCALE; v.w *= SB_SCALE;
                __half2 h0 = __float22half2_rn(make_float2(v.x, v.y));
                __half2 h1 = __float22half2_rn(make_float2(v.z, v.w));
                float2 f0 = __half22float2(h0), f1 = __half22float2(h1);
                __half2 l0 = __float22half2_rn(make_float2(v.x - f0.x, v.y - f0.y));
                __half2 l1 = __float22half2_rn(make_float2(v.z - f1.x, v.w - f1.y));
                BH[i2] = h0; BH[i2 + 1] = h1;
                BL[i2] = l0; BL[i2 + 1] = l1;
            }
        }
        __syncthreads();

        const uint32_t* Ahw = (const uint32_t*)AH;
        const uint32_t* Alw = (const uint32_t*)AL;
        const uint32_t* Bhw = (const uint32_t*)BH;
        const uint32_t* Blw = (const uint32_t*)BL;

        // ---- 2 k-steps of 16 ----
#pragma unroll
        for (int s = 0; s < 2; ++s) {
            const int ks = s * 8;   // word offset

            uint32_t bh[4][2];
#pragma unroll
            for (int ni = 0; ni < 4; ++ni) {
                const int base = (wn * 32 + ni * 8 + gid) * 20 + ks + tid;
                bh[ni][0] = Bhw[base];
                bh[ni][1] = Bhw[base + 4];
            }
            uint32_t ah[4][4];
#pragma unroll
            for (int mi = 0; mi < 4; ++mi) {
                const int base = (wm * 64 + mi * 16 + gid) * 20 + ks + tid;
                ah[mi][0] = Ahw[base];
                ah[mi][1] = Ahw[base + 160];
                ah[mi][2] = Ahw[base + 4];
                ah[mi][3] = Ahw[base + 164];
            }
            // pass 1: hi*hi
#pragma unroll
            for (int mi = 0; mi < 4; ++mi)
#pragma unroll
                for (int ni = 0; ni < 4; ++ni)
                    mma_f16(acc[mi][ni], ah[mi], bh[ni]);
            // pass 2: lo_a*hi_b
#pragma unroll
            for (int mi = 0; mi < 4; ++mi) {
                const int base = (wm * 64 + mi * 16 + gid) * 20 + ks + tid;
                uint32_t al[4];
                al[0] = Alw[base];
                al[1] = Alw[base + 160];
                al[2] = Alw[base + 4];
                al[3] = Alw[base + 164];
#pragma unroll
                for (int ni = 0; ni < 4; ++ni)
                    mma_f16(acc[mi][ni], al, bh[ni]);
            }
            // pass 3: hi_a*lo_b
#pragma unroll
            for (int ni = 0; ni < 4; ++ni) {
                const int base = (wn * 32 + ni * 8 + gid) * 20 + ks + tid;
                uint32_t bl[2];
                bl[0] = Blw[base];
                bl[1] = Blw[base + 4];
#pragma unroll
                for (int mi = 0; mi < 4; ++mi)
                    mma_f16(acc[mi][ni], ah[mi], bl);
            }
        }
    }

    // ---- epilogue (descale exactly by 2^-18) ----
#pragma unroll
    for (int mi = 0; mi < 4; ++mi) {
#pragma unroll
        for (int ni = 0; ni < 4; ++ni) {
            const int row = m0 + wm * 64 + mi * 16 + gid;
            const int col = n0 + wn * 32 + ni * 8 + 2 * tid;
            float a4[4];
#pragma unroll
            for (int c = 0; c < 4; ++c) a4[c] = acc[mi][ni][c] * DESCALE;
            if (!EPI_T) {
                *(float2*)&C[(long)row * ldc + col] = make_float2(a4[0], a4[1]);
                *(float2*)&C[(long)(row + 8) * ldc + col] = make_float2(a4[2], a4[3]);
            } else {
                C[(long)col * ldc + row]           = a4[0];
                C[(long)(col + 1) * ldc + row]     = a4[1];
                C[(long)col * ldc + row + 8]       = a4[2];
                C[(long)(col + 1) * ldc + row + 8] = a4[3];
            }
        }
    }
}

// ===========================================================================
// Pipelined tf32 GEMM (v projection, out GEMM) — unchanged from R14.
// ===========================================================================
#define LDK 36
#define TILE_F (128 * LDK)
#define STAGES 3
#define SMEM_BYTES (STAGES * 2 * TILE_F * 4)

template <bool EPI_T>
__global__ __launch_bounds__(256)
void tc_gemm(const float* __restrict__ A, const float* __restrict__ B,
             float* __restrict__ C,
             int K, int lda, int ldb, int ldc,
             long sA, long sB, long sC)
{
    extern __shared__ float smx[];
    const uint32_t sbase = smem_to_u32(smx);

    const int t   = threadIdx.x;
    const int l   = t & 31;
    const int w   = t >> 5;
    const int gid = l >> 2;
    const int tid = l & 3;
    const int wm  = w >> 2;
    const int wn  = w & 3;

    A += (long)blockIdx.z * sA;
    B += (long)blockIdx.z * sB;
    C += (long)blockIdx.z * sC;
    const int m0 = blockIdx.y * 128;
    const int n0 = blockIdx.x * 128;

    const int lr = t >> 3;
    const int lc = (t & 7) * 4;

    const int nt = K / 32;

    auto load_stage = [&](int stg, int k0) {
        const uint32_t ab = sbase + (uint32_t)stg * (2 * TILE_F * 4);
        const uint32_t bb = ab + TILE_F * 4;
#pragma unroll
        for (int p = 0; p < 4; ++p) {
            const int r = lr + p * 32;
            const uint32_t so = (uint32_t)(r * LDK + lc) * 4;
            cp16(ab + so, A + (long)(m0 + r) * lda + k0 + lc);
            cp16(bb + so, B + (long)(n0 + r) * ldb + k0 + lc);
        }
    };

    float acc[4][4][4];
#pragma unroll
    for (int mi = 0; mi < 4; ++mi)
#pragma unroll
        for (int ni = 0; ni < 4; ++ni)
#pragma unroll
            for (int c = 0; c < 4; ++c) acc[mi][ni][c] = 0.f;

    load_stage(0, 0); CP_COMMIT();
    if (nt > 1) load_stage(1, 32);
    CP_COMMIT();
    if (nt > 2) load_stage(2, 64);
    CP_COMMIT();

    int stg = 0;
#pragma unroll 1
    for (int tt = 0; tt < nt; ++tt) {
        CP_WAIT2();
        __syncthreads();

        const float* Ar = smx + stg * 2 * TILE_F;
        const float* Br = Ar + TILE_F;

#pragma unroll
        for (int s = 0; s < 4; ++s) {
            const int ks = s * 8;
            uint32_t bh[4][2];
#pragma unroll
            for (int ni = 0; ni < 4; ++ni) {
                const float* bp = &Br[(wn * 32 + ni * 8 + gid) * LDK + ks + tid];
                bh[ni][0] = tf32_rna(bp[0]);
                bh[ni][1] = tf32_rna(bp[4]);
            }
            uint32_t ah[4][4];
#pragma unroll
            for (int mi = 0; mi < 4; ++mi) {
                const float* ap = &Ar[(wm * 64 + mi * 16 + gid) * LDK + ks + tid];
                ah[mi][0] = tf32_rna(ap[0]);
                ah[mi][1] = tf32_rna(ap[8 * LDK]);
                ah[mi][2] = tf32_rna(ap[4]);
                ah[mi][3] = tf32_rna(ap[8 * LDK + 4]);
            }
#pragma unroll
            for (int mi = 0; mi < 4; ++mi)
#pragma unroll
                for (int ni = 0; ni < 4; ++ni)
                    mma_tf32(acc[mi][ni], ah[mi], bh[ni]);
        }

        __syncthreads();
        if (tt + STAGES < nt) load_stage(stg, (tt + STAGES) * 32);
        CP_COMMIT();
        stg = (stg == STAGES - 1) ? 0 : stg + 1;
    }

#pragma unroll
    for (int mi = 0; mi < 4; ++mi) {
#pragma unroll
        for (int ni = 0; ni < 4; ++ni) {
            const int row = m0 + wm * 64 + mi * 16 + gid;
            const int col = n0 + wn * 32 + ni * 8 + 2 * tid;
            const float* a4 = acc[mi][ni];
            if (!EPI_T) {
                *(float2*)&C[(long)row * ldc + col] = make_float2(a4[0], a4[1]);
                *(float2*)&C[(long)(row + 8) * ldc + col] = make_float2(a4[2], a4[3]);
            } else {
                C[(long)col * ldc + row]           = a4[0];
                C[(long)(col + 1) * ldc + row]     = a4[1];
                C[(long)col * ldc + row + 8]       = a4[2];
                C[(long)(col + 1) * ldc + row + 8] = a4[3];
            }
        }
    }
}

// ---------------------------------------------------------------------------
// Transpose x[b][c][n] -> xT[b][n][c]
// ---------------------------------------------------------------------------
__global__ __launch_bounds__(256)
void transpose_x(const float* __restrict__ x, float* __restrict__ xt)
{
    __shared__ float tile[32][33];
    const float* xb = x + (long)blockIdx.z * C_IN * NTOK;
    float* xtb = xt + (long)blockIdx.z * NTOK * C_IN;
    const int n0 = blockIdx.x * 32, c0 = blockIdx.y * 32;
    const int tx = threadIdx.x & 31, ty = threadIdx.x >> 5;
#pragma unroll
    for (int i = ty; i < 32; i += 8)
        tile[i][tx] = xb[(long)(c0 + i) * NTOK + n0 + tx];
    __syncthreads();
#pragma unroll
    for (int i = ty; i < 32; i += 8)
        xtb[(long)(n0 + i) * C_IN + c0 + tx] = tile[tx][i];
}

// ---------------------------------------------------------------------------
// Parallel column softmax over ST[b][j][i] along j, in place.
// Phase 1: each CTA covers 1024 columns x 128 rows -> online (max, sum)
//          partials. Grid (2, RS, BATCH) = 256 CTAs.
// Phase 2: combine 16 partials per column, then normalize own 128-row chunk.
// ---------------------------------------------------------------------------
#define RCHUNK (NTOK / RS)   // 128

__global__ __launch_bounds__(256)
void softmax_part(const float* __restrict__ S,
                  float* __restrict__ pm, float* __restrict__ ps)
{
    const int b  = blockIdx.z, rs = blockIdx.y;
    const int c0 = (blockIdx.x * 256 + threadIdx.x) * 4;
    const float* p = S + (long)b * NTOK * NTOK + (long)rs * RCHUNK * NTOK + c0;

    float4 m = make_float4(-CUDART_INF_F, -CUDART_INF_F,
                           -CUDART_INF_F, -CUDART_INF_F);
    float4 s = make_float4(0.f, 0.f, 0.f, 0.f);
#pragma unroll 4
    for (int j = 0; j < RCHUNK; ++j) {
        const float4 v = *(const float4*)&p[(long)j * NTOK];
        float4 mn;
        mn.x = fmaxf(m.x, v.x); mn.y = fmaxf(m.y, v.y);
        mn.z = fmaxf(m.z, v.z); mn.w = fmaxf(m.w, v.w);
        s.x = s.x * __expf(m.x - mn.x) + __expf(v.x - mn.x);
        s.y = s.y * __expf(m.y - mn.y) + __expf(v.y - mn.y);
        s.z = s.z * __expf(m.z - mn.z) + __expf(v.z - mn.z);
        s.w = s.w * __expf(m.w - mn.w) + __expf(v.w - mn.w);
        m = mn;
    }
    const long po = (long)(b * RS + rs) * NTOK + c0;
    *(float4*)&pm[po] = m;
    *(float4*)&ps[po] = s;
}

__global__ __launch_bounds__(256)
void softmax_norm(float* __restrict__ S,
                  const float* __restrict__ pm, const float* __restrict__ ps)
{
    const int b  = blockIdx.z, rs = blockIdx.y;
    const int c0 = (blockIdx.x * 256 + threadIdx.x) * 4;

    float4 m = make_float4(-CUDART_INF_F, -CUDART_INF_F,
                           -CUDART_INF_F, -CUDART_INF_F);
    float4 s = make_float4(0.f, 0.f, 0.f, 0.f);
#pragma unroll
    for (int r = 0; r < RS; ++r) {
        const long po = (long)(b * RS + r) * NTOK + c0;
        const float4 pmr = *(const float4*)&pm[po];
        const float4 psr = *(const float4*)&ps[po];
        float4 mn;
        mn.x = fmaxf(m.x, pmr.x); mn.y = fmaxf(m.y, pmr.y);
        mn.z = fmaxf(m.z, pmr.z); mn.w = fmaxf(m.w, pmr.w);
        s.x = s.x * __expf(m.x - mn.x) + psr.x * __expf(pmr.x - mn.x);
        s.y = s.y * __expf(m.y - mn.y) + psr.y * __expf(pmr.y - mn.y);
        s.z = s.z * __expf(m.z - mn.z) + psr.z * __expf(pmr.z - mn.z);
        s.w = s.w * __expf(m.w - mn.w) + psr.w * __expf(pmr.w - mn.w);
        m = mn;
    }
    const float4 inv = make_float4(1.f / s.x, 1.f / s.y, 1.f / s.z, 1.f / s.w);

    float* p = S + (long)b * NTOK * NTOK + (long)rs * RCHUNK * NTOK + c0;
#pragma unroll 4
    for (int j = 0; j < RCHUNK; ++j) {
        float4 v = *(const float4*)&p[(long)j * NTOK];
        v.x = __expf(v.x - m.x) * inv.x;
        v.y = __expf(v.y - m.y) * inv.y;
        v.z = __expf(v.z - m.z) * inv.z;
        v.w = __expf(v.w - m.w) * inv.w;
        *(float4*)&p[(long)j * NTOK] = v;
    }
}

// ---------------------------------------------------------------------------
// Launch
// ---------------------------------------------------------------------------
extern "C" void kernel_launch(void* const* d_in, const int* in_sizes, int n_in,
                              void* d_out, int out_size)
{
    const float* x  = nullptr;
    const float* Wq = nullptr;
    const float* Wk = nullptr;
    const float* Wv = nullptr;
    for (int i = 0; i < n_in; ++i) {
        const float* p = (const float*)d_in[i];
        if (in_sizes[i] == BATCH * C_IN * NTOK)      x = p;
        else if (in_sizes[i] == C_OUT * C_IN)        Wv = p;
        else if (in_sizes[i] == C_KEY * C_IN) {
            if (!Wq) Wq = p; else Wk = p;
        }
    }

    float *xt, *qt, *kt, *v, *s, *pm, *ps;
    cudaGetSymbolAddress((void**)&xt, g_xt);
    cudaGetSymbolAddress((void**)&qt, g_qt);
    cudaGetSymbolAddress((void**)&kt, g_kt);
    cudaGetSymbolAddress((void**)&v,  g_v);
    cudaGetSymbolAddress((void**)&s,  g_s);
    cudaGetSymbolAddress((void**)&pm, g_pm);
    cudaGetSymbolAddress((void**)&ps, g_ps);
    float* out = (float*)d_out;

    cudaFuncSetAttribute(tc_gemm<true >, cudaFuncAttributeMaxDynamicSharedMemorySize, SMEM_BYTES);
    cudaFuncSetAttribute(tc_gemm<false>, cudaFuncAttributeMaxDynamicSharedMemorySize, SMEM_BYTES);

    // 0) xT[b][n][c] = x[b][c][n]
    transpose_x<<<dim3(NTOK / 32, C_IN / 32, BATCH), 256>>>(x, xt);

    // 1) q/k projections: fp16-split, epilogue-T -> qT/kT[n][o]
    hp_gemm<true><<<dim3(NTOK / 128, C_KEY / 128, BATCH), 256>>>(
        Wq, xt, qt, C_IN, C_IN, C_IN, C_KEY,
        0L, (long)NTOK * C_IN, (long)NTOK * C_KEY);
    hp_gemm<true><<<dim3(NTOK / 128, C_KEY / 128, BATCH), 256>>>(
        Wk, xt, kt, C_IN, C_IN, C_IN, C_KEY,
        0L, (long)NTOK * C_IN, (long)NTOK * C_KEY);

    // 2) v projection: tf32 single, epilogue-N -> v[c][i]
    tc_gemm<false><<<dim3(NTOK / 128, C_OUT / 128, BATCH), 256, SMEM_BYTES>>>(
        Wv, xt, v, C_IN, C_IN, C_IN, NTOK,
        0L, (long)NTOK * C_IN, (long)C_OUT * NTOK);

    // 3) sim, transposed: ST[j][i] = sum_c qT[j,c] * kT[i,c]  (fp16-split)
    hp_gemm<false><<<dim3(NTOK / 128, NTOK / 128, BATCH), 256>>>(
        qt, kt, s, C_KEY, C_KEY, C_KEY, NTOK,
        (long)NTOK * C_KEY, (long)NTOK * C_KEY, (long)NTOK * NTOK);

    // 4) parallel column softmax (in place): ST -> attnT
    softmax_part<<<dim3(NTOK / 1024, RS, BATCH), 256>>>(s, pm, ps);
    softmax_norm<<<dim3(NTOK / 1024, RS, BATCH), 256>>>(s, pm, ps);

    // 5) out: D[c,m] = sum_i v[c,i] * attnT[m,i]; epilogue-T -> out[m][c]
    tc_gemm<true><<<dim3(NTOK / 128, C_OUT / 128, BATCH), 256, SMEM_BYTES>>>(
        v, s, out, NTOK, NTOK, NTOK, C_OUT,
        (long)C_OUT * NTOK, (long)NTOK * NTOK, (long)NTOK * C_OUT);
}

// round 16
// speedup vs baseline: 2.7188x; 1.0669x over previous
#include <cuda_runtime.h>
#include <cuda_fp16.h>
#include <math_constants.h>
#include <cstdint>

// Problem constants
#define BATCH 8
#define C_IN  512
#define C_OUT 512
#define C_KEY 256
#define NTOK  2048

// ---------------------------------------------------------------------------
// Scratch (__device__ globals; no cudaMalloc allowed)
// ---------------------------------------------------------------------------
__device__ float g_xt[BATCH * NTOK * C_IN];   // xT[b][n][c]
__device__ float g_qt[BATCH * NTOK * C_KEY];  // qT[b][n][ck]
__device__ float g_kt[BATCH * NTOK * C_KEY];  // kT[b][n][ck]
__device__ float g_v [BATCH * C_OUT * NTOK];  // v[b][c][i]  (i contiguous)
__device__ float g_s [BATCH * NTOK * NTOK];   // ST[b][j][i] -> attnT in place

#define RS 16                                  // softmax row-split
__device__ float g_pm[BATCH * RS * NTOK];      // partial max
__device__ float g_ps[BATCH * RS * NTOK];      // partial sum

// ---------------------------------------------------------------------------
// Base-PTX helpers (valid on .target sm_103 — no tcgen05)
// ---------------------------------------------------------------------------
__device__ __forceinline__ void mma_f16(float* d, const uint32_t* a,
                                        const uint32_t* b)
{
    asm volatile(
        "mma.sync.aligned.m16n8k16.row.col.f32.f16.f16.f32 "
        "{%0,%1,%2,%3}, {%4,%5,%6,%7}, {%8,%9}, {%0,%1,%2,%3};"
        : "+f"(d[0]), "+f"(d[1]), "+f"(d[2]), "+f"(d[3])
        : "r"(a[0]), "r"(a[1]), "r"(a[2]), "r"(a[3]),
          "r"(b[0]), "r"(b[1]));
}

// ===========================================================================
// fp16 tensor-core GEMM:  D[m,n] = sum_k A[m,k] * B[n,k]  (K-major fp32 in)
//
// SPLIT=true : 2xfp16 precision. hi = rn_f16(x*scale), lo = rn_f16(x*scale-hi)
//   3 MMA passes (hh, lo_a*hi_b, hi_a*lo_b) => product error ~2^-24.
//   Power-of-2 pre-scales (SA=1024, SB=256) keep lo out of fp16-subnormal
//   territory; epilogue multiplies by 2^-18 exactly.
// SPLIT=false: single pass, unit scales. Unit roundoff 2^-11 — identical to
//   tf32 single-pass (same effective mantissa), at half the mma count.
//
// CTA 128x128, BK=32, 256 thr, 8 warps of 64x32 warp tiles. m16n8k16.
// smem tiles [128][40] halfs (stride 20 words: fragment pattern gid*20+tid
// covers all banks conflict-free).  EPI_T : store C[n][m] instead of C[m][n].
// ===========================================================================
#define HLDK 40
#define HTILE2 (128 * HLDK / 2)      // half2 per tile = 2560 (10240 B)

template <bool SPLIT, bool EPI_T>
__global__ __launch_bounds__(256, 2)
void hp_gemm(const float* __restrict__ A, const float* __restrict__ B,
             float* __restrict__ C,
             int K, int lda, int ldb, int ldc,
             long sA, long sB, long sC)
{
    constexpr float SAs = SPLIT ? 1024.0f : 1.0f;
    constexpr float SBs = SPLIT ? 256.0f  : 1.0f;
    constexpr float DSC = SPLIT ? (1.0f / (1024.0f * 256.0f)) : 1.0f;

    __shared__ __align__(16) __half2 AH[HTILE2];
    __shared__ __align__(16) __half2 AL[SPLIT ? HTILE2 : 2];
    __shared__ __align__(16) __half2 BH[HTILE2];
    __shared__ __align__(16) __half2 BL[SPLIT ? HTILE2 : 2];

    const int t   = threadIdx.x;
    const int l   = t & 31;
    const int w   = t >> 5;
    const int gid = l >> 2;
    const int tid = l & 3;
    const int wm  = w >> 2;        // 0..1 -> m offset wm*64
    const int wn  = w & 3;         // 0..3 -> n offset wn*32

    A += (long)blockIdx.z * sA;
    B += (long)blockIdx.z * sB;
    C += (long)blockIdx.z * sC;
    const int m0 = blockIdx.y * 128;
    const int n0 = blockIdx.x * 128;

    const int lr  = t >> 3;        // 0..31
    const int lc4 = (t & 7) * 4;   // 0..28

    float acc[4][4][4];
#pragma unroll
    for (int mi = 0; mi < 4; ++mi)
#pragma unroll
        for (int ni = 0; ni < 4; ++ni)
#pragma unroll
            for (int c = 0; c < 4; ++c) acc[mi][ni][c] = 0.f;

    const int nt = K / 32;
#pragma unroll 1
    for (int tt = 0; tt < nt; ++tt) {
        const int k0 = tt * 32;
        __syncthreads();    // previous compute done before overwrite

        // ---- loader: fp32 -> (scaled) fp16 hi(/lo) into smem ----
#pragma unroll
        for (int p = 0; p < 4; ++p) {
            const int r  = lr + p * 32;
            const int i2 = r * (HLDK / 2) + (t & 7) * 2;
            {
                float4 v = *(const float4*)(A + (long)(m0 + r) * lda + k0 + lc4);
                v.x *= SAs; v.y *= SAs; v.z *= SAs; v.w *= SAs;
                __half2 h0 = __float22half2_rn(make_float2(v.x, v.y));
                __half2 h1 = __float22half2_rn(make_float2(v.z, v.w));
                AH[i2] = h0; AH[i2 + 1] = h1;
                if (SPLIT) {
                    float2 f0 = __half22float2(h0), f1 = __half22float2(h1);
                    AL[i2]     = __float22half2_rn(make_float2(v.x - f0.x, v.y - f0.y));
                    AL[i2 + 1] = __float22half2_rn(make_float2(v.z - f1.x, v.w - f1.y));
                }
            }
            {
                float4 v = *(const float4*)(B + (long)(n0 + r) * ldb + k0 + lc4);
                v.x *= SBs; v.y *= SBs; v.z *= SBs; v.w *= SBs;
                __half2 h0 = __float22half2_rn(make_float2(v.x, v.y));
                __half2 h1 = __float22half2_rn(make_float2(v.z, v.w));
                BH[i2] = h0; BH[i2 + 1] = h1;
                if (SPLIT) {
                    float2 f0 = __half22float2(h0), f1 = __half22float2(h1);
                    BL[i2]     = __float22half2_rn(make_float2(v.x - f0.x, v.y - f0.y));
                    BL[i2 + 1] = __float22half2_rn(make_float2(v.z - f1.x, v.w - f1.y));
                }
            }
        }
        __syncthreads();

        const uint32_t* Ahw = (const uint32_t*)AH;
        const uint32_t* Alw = (const uint32_t*)AL;
        const uint32_t* Bhw = (const uint32_t*)BH;
        const uint32_t* Blw = (const uint32_t*)BL;

        // ---- 2 k-steps of 16 ----
#pragma unroll
        for (int s = 0; s < 2; ++s) {
            const int ks = s * 8;   // word offset

            uint32_t bh[4][2];
#pragma unroll
            for (int ni = 0; ni < 4; ++ni) {
                const int base = (wn * 32 + ni * 8 + gid) * 20 + ks + tid;
                bh[ni][0] = Bhw[base];
                bh[ni][1] = Bhw[base + 4];
            }
            uint32_t ah[4][4];
#pragma unroll
            for (int mi = 0; mi < 4; ++mi) {
                const int base = (wm * 64 + mi * 16 + gid) * 20 + ks + tid;
                ah[mi][0] = Ahw[base];
                ah[mi][1] = Ahw[base + 160];
                ah[mi][2] = Ahw[base + 4];
                ah[mi][3] = Ahw[base + 164];
            }
            // pass 1: hi*hi
#pragma unroll
            for (int mi = 0; mi < 4; ++mi)
#pragma unroll
                for (int ni = 0; ni < 4; ++ni)
                    mma_f16(acc[mi][ni], ah[mi], bh[ni]);
            if (SPLIT) {
                // pass 2: lo_a*hi_b
#pragma unroll
                for (int mi = 0; mi < 4; ++mi) {
                    const int base = (wm * 64 + mi * 16 + gid) * 20 + ks + tid;
                    uint32_t al[4];
                    al[0] = Alw[base];
                    al[1] = Alw[base + 160];
                    al[2] = Alw[base + 4];
                    al[3] = Alw[base + 164];
#pragma unroll
                    for (int ni = 0; ni < 4; ++ni)
                        mma_f16(acc[mi][ni], al, bh[ni]);
                }
                // pass 3: hi_a*lo_b
#pragma unroll
                for (int ni = 0; ni < 4; ++ni) {
                    const int base = (wn * 32 + ni * 8 + gid) * 20 + ks + tid;
                    uint32_t bl[2];
                    bl[0] = Blw[base];
                    bl[1] = Blw[base + 4];
#pragma unroll
                    for (int mi = 0; mi < 4; ++mi)
                        mma_f16(acc[mi][ni], ah[mi], bl);
                }
            }
        }
    }

    // ---- epilogue (descale exactly by 2^-18 when SPLIT) ----
#pragma unroll
    for (int mi = 0; mi < 4; ++mi) {
#pragma unroll
        for (int ni = 0; ni < 4; ++ni) {
            const int row = m0 + wm * 64 + mi * 16 + gid;
            const int col = n0 + wn * 32 + ni * 8 + 2 * tid;
            float a4[4];
#pragma unroll
            for (int c = 0; c < 4; ++c) a4[c] = acc[mi][ni][c] * DSC;
            if (!EPI_T) {
                *(float2*)&C[(long)row * ldc + col] = make_float2(a4[0], a4[1]);
                *(float2*)&C[(long)(row + 8) * ldc + col] = make_float2(a4[2], a4[3]);
            } else {
                C[(long)col * ldc + row]           = a4[0];
                C[(long)(col + 1) * ldc + row]     = a4[1];
                C[(long)col * ldc + row + 8]       = a4[2];
                C[(long)(col + 1) * ldc + row + 8] = a4[3];
            }
        }
    }
}

// ---------------------------------------------------------------------------
// Transpose x[b][c][n] -> xT[b][n][c]
// ---------------------------------------------------------------------------
__global__ __launch_bounds__(256)
void transpose_x(const float* __restrict__ x, float* __restrict__ xt)
{
    __shared__ float tile[32][33];
    const float* xb = x + (long)blockIdx.z * C_IN * NTOK;
    float* xtb = xt + (long)blockIdx.z * NTOK * C_IN;
    const int n0 = blockIdx.x * 32, c0 = blockIdx.y * 32;
    const int tx = threadIdx.x & 31, ty = threadIdx.x >> 5;
#pragma unroll
    for (int i = ty; i < 32; i += 8)
        tile[i][tx] = xb[(long)(c0 + i) * NTOK + n0 + tx];
    __syncthreads();
#pragma unroll
    for (int i = ty; i < 32; i += 8)
        xtb[(long)(n0 + i) * C_IN + c0 + tx] = tile[tx][i];
}

// ---------------------------------------------------------------------------
// Parallel column softmax over ST[b][j][i] along j, in place.
// Phase 1: per (row-chunk, column-block) online (max,sum) partials.
// Phase 2: combine RS partials per column, normalize own chunk.
// ---------------------------------------------------------------------------
#define RCHUNK (NTOK / RS)   // 128

__global__ __launch_bounds__(256)
void softmax_part(const float* __restrict__ S,
                  float* __restrict__ pm, float* __restrict__ ps)
{
    const int b  = blockIdx.z, rs = blockIdx.y;
    const int c0 = (blockIdx.x * 256 + threadIdx.x) * 4;
    const float* p = S + (long)b * NTOK * NTOK + (long)rs * RCHUNK * NTOK + c0;

    float4 m = make_float4(-CUDART_INF_F, -CUDART_INF_F,
                           -CUDART_INF_F, -CUDART_INF_F);
    float4 s = make_float4(0.f, 0.f, 0.f, 0.f);
#pragma unroll 4
    for (int j = 0; j < RCHUNK; ++j) {
        const float4 v = *(const float4*)&p[(long)j * NTOK];
        float4 mn;
        mn.x = fmaxf(m.x, v.x); mn.y = fmaxf(m.y, v.y);
        mn.z = fmaxf(m.z, v.z); mn.w = fmaxf(m.w, v.w);
        s.x = s.x * __expf(m.x - mn.x) + __expf(v.x - mn.x);
        s.y = s.y * __expf(m.y - mn.y) + __expf(v.y - mn.y);
        s.z = s.z * __expf(m.z - mn.z) + __expf(v.z - mn.z);
        s.w = s.w * __expf(m.w - mn.w) + __expf(v.w - mn.w);
        m = mn;
    }
    const long po = (long)(b * RS + rs) * NTOK + c0;
    *(float4*)&pm[po] = m;
    *(float4*)&ps[po] = s;
}

__global__ __launch_bounds__(256)
void softmax_norm(float* __restrict__ S,
                  const float* __restrict__ pm, const float* __restrict__ ps)
{
    const int b  = blockIdx.z, rs = blockIdx.y;
    const int c0 = (blockIdx.x * 256 + threadIdx.x) * 4;

    float4 m = make_float4(-CUDART_INF_F, -CUDART_INF_F,
                           -CUDART_INF_F, -CUDART_INF_F);
    float4 s = make_float4(0.f, 0.f, 0.f, 0.f);
#pragma unroll
    for (int r = 0; r < RS; ++r) {
        const long po = (long)(b * RS + r) * NTOK + c0;
        const float4 pmr = *(const float4*)&pm[po];
        const float4 psr = *(const float4*)&ps[po];
        float4 mn;
        mn.x = fmaxf(m.x, pmr.x); mn.y = fmaxf(m.y, pmr.y);
        mn.z = fmaxf(m.z, pmr.z); mn.w = fmaxf(m.w, pmr.w);
        s.x = s.x * __expf(m.x - mn.x) + psr.x * __expf(pmr.x - mn.x);
        s.y = s.y * __expf(m.y - mn.y) + psr.y * __expf(pmr.y - mn.y);
        s.z = s.z * __expf(m.z - mn.z) + psr.z * __expf(pmr.z - mn.z);
        s.w = s.w * __expf(m.w - mn.w) + psr.w * __expf(pmr.w - mn.w);
        m = mn;
    }
    const float4 inv = make_float4(1.f / s.x, 1.f / s.y, 1.f / s.z, 1.f / s.w);

    float* p = S + (long)b * NTOK * NTOK + (long)rs * RCHUNK * NTOK + c0;
#pragma unroll 4
    for (int j = 0; j < RCHUNK; ++j) {
        float4 v = *(const float4*)&p[(long)j * NTOK];
        v.x = __expf(v.x - m.x) * inv.x;
        v.y = __expf(v.y - m.y) * inv.y;
        v.z = __expf(v.z - m.z) * inv.z;
        v.w = __expf(v.w - m.w) * inv.w;
        *(float4*)&p[(long)j * NTOK] = v;
    }
}

// ---------------------------------------------------------------------------
// Launch
// ---------------------------------------------------------------------------
extern "C" void kernel_launch(void* const* d_in, const int* in_sizes, int n_in,
                              void* d_out, int out_size)
{
    const float* x  = nullptr;
    const float* Wq = nullptr;
    const float* Wk = nullptr;
    const float* Wv = nullptr;
    for (int i = 0; i < n_in; ++i) {
        const float* p = (const float*)d_in[i];
        if (in_sizes[i] == BATCH * C_IN * NTOK)      x = p;
        else if (in_sizes[i] == C_OUT * C_IN)        Wv = p;
        else if (in_sizes[i] == C_KEY * C_IN) {
            if (!Wq) Wq = p; else Wk = p;
        }
    }

    float *xt, *qt, *kt, *v, *s, *pm, *ps;
    cudaGetSymbolAddress((void**)&xt, g_xt);
    cudaGetSymbolAddress((void**)&qt, g_qt);
    cudaGetSymbolAddress((void**)&kt, g_kt);
    cudaGetSymbolAddress((void**)&v,  g_v);
    cudaGetSymbolAddress((void**)&s,  g_s);
    cudaGetSymbolAddress((void**)&pm, g_pm);
    cudaGetSymbolAddress((void**)&ps, g_ps);
    float* out = (float*)d_out;

    // 0) xT[b][n][c] = x[b][c][n]
    transpose_x<<<dim3(NTOK / 32, C_IN / 32, BATCH), 256>>>(x, xt);

    // 1) q/k projections: fp16-split, epilogue-T -> qT/kT[n][o]
    hp_gemm<true, true><<<dim3(NTOK / 128, C_KEY / 128, BATCH), 256>>>(
        Wq, xt, qt, C_IN, C_IN, C_IN, C_KEY,
        0L, (long)NTOK * C_IN, (long)NTOK * C_KEY);
    hp_gemm<true, true><<<dim3(NTOK / 128, C_KEY / 128, BATCH), 256>>>(
        Wk, xt, kt, C_IN, C_IN, C_IN, C_KEY,
        0L, (long)NTOK * C_IN, (long)NTOK * C_KEY);

    // 2) v projection: fp16 single pass (same 2^-11 roundoff as tf32, half
    //    the mma count), epilogue-N -> v[c][i]
    hp_gemm<false, false><<<dim3(NTOK / 128, C_OUT / 128, BATCH), 256>>>(
        Wv, xt, v, C_IN, C_IN, C_IN, NTOK,
        0L, (long)NTOK * C_IN, (long)C_OUT * NTOK);

    // 3) sim, transposed: ST[j][i] = sum_c qT[j,c] * kT[i,c]  (fp16-split)
    hp_gemm<true, false><<<dim3(NTOK / 128, NTOK / 128, BATCH), 256>>>(
        qt, kt, s, C_KEY, C_KEY, C_KEY, NTOK,
        (long)NTOK * C_KEY, (long)NTOK * C_KEY, (long)NTOK * NTOK);

    // 4) parallel column softmax (in place): ST -> attnT
    softmax_part<<<dim3(NTOK / 1024, RS, BATCH), 256>>>(s, pm, ps);
    softmax_norm<<<dim3(NTOK / 1024, RS, BATCH), 256>>>(s, pm, ps);

    // 5) out: D[c,m] = sum_i v[c,i] * attnT[m,i]; fp16 single pass,
    //    epilogue-T -> out[m][c]
    hp_gemm<false, true><<<dim3(NTOK / 128, C_OUT / 128, BATCH), 256>>>(
        v, s, out, NTOK, NTOK, NTOK, C_OUT,
        (long)C_OUT * NTOK, (long)NTOK * NTOK, (long)NTOK * C_OUT);
}